// round 12
// baseline (speedup 1.0000x reference)
#include <cuda_runtime.h>

// ---- problem constants ----
#define A_   3
#define H_   128
#define W_   128
#define ATTRS 7
#define B_   64
#define T_   2
#define NCELLS (B_*A_*H_*W_)                   // 3,145,728
#define NROWS (NCELLS/W_)                      // 24576 rows of 128 cells
#define ROWS_PER_BATCH (A_*H_)                 // 384
#define THREADS 128
#define NWARPS  (THREADS/32)                   // 4
#define GRID    1024
#define TOTWARPS (GRID*NWARPS)                 // 4096 -> 6 rows/warp exact
#define F4PR (W_*ATTRS/4)                      // 224 float4 per row = 3584 B
#define LINES_PER_ROW 28                       // 3584/128

// ---- persistent device state (zero-init at load; self-resetting) ----
__device__ double       g_acc[6] = {0, 0, 0, 0, 0, 0};
__device__ unsigned int g_done   = 0;

struct Tgt { float cx, cy, bw, bh, ar, cl; int key; };

__device__ __forceinline__ Tgt make_tgt(const float* __restrict__ boxes,
                                        const int*   __restrict__ labels,
                                        const float* __restrict__ areas,
                                        int b, int t) {
    const float* bx = boxes + (size_t)(b * T_ + t) * 4;
    float x1 = __ldg(bx + 0), y1 = __ldg(bx + 1);
    float x2 = __ldg(bx + 2), y2 = __ldg(bx + 3);
    Tgt o;
    o.cx = (x1 + x2) * 0.5f;
    o.cy = (y1 + y2) * 0.5f;
    o.bw = x2 - x1;
    o.bh = y2 - y1;
    o.ar = (o.bw - o.cx) * (o.bh - o.cy);    // area_t in reference

    float ar = __ldg(areas + b * T_ + t);
    float d0 = fabsf(10440.0f  - ar);        // 116*90
    float d1 = fabsf(30888.0f  - ar);        // 156*198
    float d2 = fabsf(121598.0f - ar);        // 373*326
    int   an = 0; float m = d0;
    if (d1 < m) { m = d1; an = 1; }
    if (d2 < m) { an = 2; }

    int cX = (int)((o.bw - o.cx) * 0.125f);  // /8 exact
    int cY = (int)((o.bh - o.cy) * 0.125f);
    o.key = (an << 16) | (cX << 8) | cY;

    int lab = __ldg(labels + b * T_ + t);
    o.cl = (t == 0) ? ((lab == 1) ? 1.0f : 0.0f)
                    : ((lab == 2) ? 1.0f : 0.0f);
    return o;
}

// ============================================================
// Warp-autonomous double-buffered pipeline over 128-cell rows,
// plus explicit L2 prefetch of row r+2*TOTWARPS (depth-3 at L2).
// ============================================================
__global__ __launch_bounds__(THREADS, 7)
void yolo_fused(const float4* __restrict__ q,
                const float*  __restrict__ boxes,
                const int*    __restrict__ labels,
                const float*  __restrict__ areas,
                float* __restrict__ out) {
    __shared__ float4 s[NWARPS][2][F4PR];      // 4 warps x 2 x 3.5 KB = 28 KB
    __shared__ int    skey[B_ * T_];
    __shared__ float  shalf[B_];               // 0.5*min(area_t0, area_t1)
    __shared__ float  red[6][NWARPS];

    const int tid  = threadIdx.x;
    const int wid  = tid >> 5;
    const int lane = tid & 31;
    const int gw   = blockIdx.x * NWARPS + wid;   // global warp id

    // per-block precompute: all 128 (b,t) keys + halved min target area
    {
        Tgt t = make_tgt(boxes, labels, areas, tid >> 1, tid & 1);
        skey[tid] = t.key;
        if ((tid & 1) == 0) {
            Tgt t1 = make_tgt(boxes, labels, areas, tid >> 1, 1);
            shalf[tid >> 1] = 0.5f * fminf(t.ar, t1.ar);
        }
    }
    __syncthreads();   // skey/shalf visible before any warp uses them

    float sx = 0.f, sy = 0.f, sw = 0.f, sh = 0.f, sc = 0.f, sl = 0.f;

    // prologue: async-load first row into this warp's buffer 0
    {
        unsigned dst = (unsigned)__cvta_generic_to_shared(&s[wid][0][lane]);
        const float4* src = q + (size_t)gw * F4PR + lane;
        #pragma unroll
        for (int m = 0; m < 7; m++)
            asm volatile("cp.async.cg.shared.global.L2::256B [%0], [%1], 16;"
                         :: "r"(dst + m * 32 * 16), "l"(src + m * 32));
        asm volatile("cp.async.commit_group;");
    }

    int buf = 0;
    for (int r = gw; r < NROWS; r += TOTWARPS) {
        // prefetch next row into the other buffer
        int nr = r + TOTWARPS;
        if (nr < NROWS) {
            unsigned dst = (unsigned)__cvta_generic_to_shared(&s[wid][buf ^ 1][lane]);
            const float4* src = q + (size_t)nr * F4PR + lane;
            #pragma unroll
            for (int m = 0; m < 7; m++)
                asm volatile("cp.async.cg.shared.global.L2::256B [%0], [%1], 16;"
                             :: "r"(dst + m * 32 * 16), "l"(src + m * 32));
        }
        asm volatile("cp.async.commit_group;");

        // L2-tier prefetch of the row after next (no smem, no barrier cost)
        int pr = r + 2 * TOTWARPS;
        if (pr < NROWS && lane < LINES_PER_ROW) {
            const char* p = (const char*)(q + (size_t)pr * F4PR) + lane * 128;
            asm volatile("prefetch.global.L2 [%0];" :: "l"(p));
        }

        asm volatile("cp.async.wait_group 1;" ::: "memory");  // this row done
        __syncwarp();   // lanes see each other's cp.async data

        // row-uniform indices: r = b*384 + a*128 + i
        int b  = r / ROWS_PER_BATCH;
        int rr = r - b * ROWS_PER_BATCH;
        int a  = rr >> 7;
        int i  = rr & (H_ - 1);
        int j0 = lane * 4;

        int   k0   = skey[2 * b], k1 = skey[2 * b + 1];
        float hmin = shalf[b];

        // my 4 cells: 28 floats via 7 conflict-free LDS.128
        float f[28];
        float4* fp = reinterpret_cast<float4*>(f);
        #pragma unroll
        for (int m = 0; m < 7; m++)
            fp[m] = s[wid][buf][lane * 7 + m];

        int gkey = (a << 16) | (i << 8) | j0;
        bool gex = (gkey == (k0 & ~3)) || (gkey == (k1 & ~3));

        // ---- fast path: guard + product of (1-conf) ----
        float prod = 1.0f;
        unsigned rare = gex ? 0xFu : 0u;
        #pragma unroll
        for (int k = 0; k < 4; k++) {
            float w    = f[7 * k + 2];
            float h    = f[7 * k + 3];
            float conf = f[7 * k + 4];
            // suppress requires inter > area_t/2 and inter <= w*h:
            // w*h < 0.5*min(area_t) guarantees no suppress (exact scaling).
            bool  rb = (w * h >= hmin);
            rare |= (unsigned)rb << k;
            prod *= (rb | gex) ? 1.0f : (1.0f - conf);  // (1-conf) >= 2^-24
        }

        // ---- cold path: exact cells / possible suppress (inline) ----
        if (__builtin_expect(rare != 0u, 0)) {
            Tgt t0 = make_tgt(boxes, labels, areas, b, 0);
            Tgt t1 = make_tgt(boxes, labels, areas, b, 1);
            float fi = (float)i;
            #pragma unroll
            for (int k = 0; k < 4; k++) {
                if (!((rare >> k) & 1u)) continue;
                float xr   = f[7 * k + 0];
                float yr   = f[7 * k + 1];
                float w    = f[7 * k + 2];
                float h    = f[7 * k + 3];
                float conf = f[7 * k + 4];
                float fj   = (float)(j0 + k);
                float xp = xr - fi, yp = yr - fj;
                int key  = gkey + k;

                if (key == t1.key || key == t0.key) {
                    bool  is1 = (key == t1.key);   // target 1 wins overwrite
                    float cx = is1 ? t1.cx : t0.cx;
                    float cy = is1 ? t1.cy : t0.cy;
                    float bw = is1 ? t1.bw : t0.bw;
                    float bh = is1 ? t1.bh : t0.bh;
                    float tc = is1 ? t1.cl : t0.cl;

                    float dX = xp - (cx - fi);
                    float dY = yp - (cy - fj);
                    float dW = w - bw;
                    float dH = h - bh;
                    sx += dX * dX;  sy += dY * dY;
                    sw += dW * dW;  sh += dH * dH;

                    sc += -fmaxf(__logf(conf), -100.0f);
                    float p0 = f[7 * k + 5];
                    float p1 = f[7 * k + 6];
                    if (tc != 0.0f) {
                        sl += -fmaxf(__logf(p0), -100.0f)
                            -  fmaxf(__logf(p1), -100.0f);
                    } else {
                        sl += -fmaxf(__logf(1.0f - p0), -100.0f)
                            -  fmaxf(__logf(1.0f - p1), -100.0f);
                    }
                } else {
                    // full suppress test (division-free)
                    float hw = 0.5f * w, hh = 0.5f * h;
                    float px1 = xp - hw, px2 = xp + hw;
                    float py1 = yp - hh, py2 = yp + hh;
                    float area_p = (px2 - px1) * (py2 - py1);

                    float ix0 = fmaxf(fminf(px2, t0.bw) - fmaxf(px1, t0.cx), 0.0f);
                    float iy0 = fmaxf(fminf(py2, t0.bh) - fmaxf(py1, t0.cy), 0.0f);
                    float in0 = ix0 * iy0;
                    bool sup  = in0 > 0.5f * (area_p + t0.ar - in0 + 1e-16f);

                    float ix1 = fmaxf(fminf(px2, t1.bw) - fmaxf(px1, t1.cx), 0.0f);
                    float iy1 = fmaxf(fminf(py2, t1.bh) - fmaxf(py1, t1.cy), 0.0f);
                    float in1 = ix1 * iy1;
                    sup = sup || (in1 > 0.5f * (area_p + t1.ar - in1 + 1e-16f));

                    if (!sup)
                        sc += -fmaxf(__logf(1.0f - conf), -100.0f);
                }
            }
        }
        sc -= __logf(prod);                    // one MUFU per 4 cells

        __syncwarp();                          // all lanes done reading s[wid][buf]
        buf ^= 1;
    }

    // -- reduction: warp shuffle -> block smem -> 6 double atomics --
    #pragma unroll
    for (int o = 16; o > 0; o >>= 1) {
        sx += __shfl_down_sync(0xffffffffu, sx, o);
        sy += __shfl_down_sync(0xffffffffu, sy, o);
        sw += __shfl_down_sync(0xffffffffu, sw, o);
        sh += __shfl_down_sync(0xffffffffu, sh, o);
        sc += __shfl_down_sync(0xffffffffu, sc, o);
        sl += __shfl_down_sync(0xffffffffu, sl, o);
    }
    if (lane == 0) {
        red[0][wid] = sx; red[1][wid] = sy; red[2][wid] = sw;
        red[3][wid] = sh; red[4][wid] = sc; red[5][wid] = sl;
    }
    __syncthreads();
    if (tid < 6) {
        float acc = 0.f;
        #pragma unroll
        for (int wv = 0; wv < NWARPS; wv++) acc += red[tid][wv];
        atomicAdd(&g_acc[tid], (double)acc);
    }
    __syncthreads();

    // -- last-block-done finalization --
    if (tid == 0) {
        __threadfence();
        unsigned int old = atomicAdd(&g_done, 1u);
        if (old == gridDim.x - 1) {
            __threadfence();
            double N = (double)NCELLS;
            double xL = g_acc[0] / N;
            double yL = g_acc[1] / N;
            double wL = g_acc[2] / N;
            double hL = g_acc[3] / N;
            double confL = g_acc[4] / N;
            double clsL  = g_acc[5] / (2.0 * N);
            double loss = 2.5 * (xL + yL) + 2.5 * (wL + hL) + confL + clsL;
            out[0] = (float)loss;
            out[1] = (float)xL;
            out[2] = (float)yL;
            out[3] = (float)wL;
            out[4] = (float)hL;
            out[5] = (float)confL;
            out[6] = (float)clsL;
            #pragma unroll
            for (int i2 = 0; i2 < 6; i2++) g_acc[i2] = 0.0;
            g_done = 0;
        }
    }
}

extern "C" void kernel_launch(void* const* d_in, const int* in_sizes, int n_in,
                              void* d_out, int out_size) {
    const float* output = (const float*)d_in[0];
    const float* boxes  = (const float*)d_in[1];
    const int*   labels = (const int*)  d_in[2];
    const float* areas  = (const float*)d_in[3];

    yolo_fused<<<GRID, THREADS>>>((const float4*)output,
                                  boxes, labels, areas, (float*)d_out);
}

// round 13
// speedup vs baseline: 1.1186x; 1.1186x over previous
#include <cuda_runtime.h>

// ---- problem constants ----
#define A_   3
#define H_   128
#define W_   128
#define ATTRS 7
#define B_   64
#define T_   2
#define NCELLS (B_*A_*H_*W_)                   // 3,145,728
#define NROWS (NCELLS/W_)                      // 24576 rows of 128 cells
#define ROWS_PER_BATCH (A_*H_)                 // 384
#define THREADS 128
#define NWARPS  (THREADS/32)                   // 4
#define GRID    1024
#define TOTWARPS (GRID*NWARPS)                 // 4096 -> 6 rows/warp exact
#define F4PR (W_*ATTRS/4)                      // 224 float4 per row = 3584 B

// ---- persistent device state (zero-init at load; self-resetting) ----
__device__ double       g_acc[6] = {0, 0, 0, 0, 0, 0};
__device__ unsigned int g_done   = 0;

struct Tgt { float cx, cy, bw, bh, ar, cl; int key; };

__device__ __forceinline__ Tgt make_tgt(const float* __restrict__ boxes,
                                        const int*   __restrict__ labels,
                                        const float* __restrict__ areas,
                                        int b, int t) {
    const float* bx = boxes + (size_t)(b * T_ + t) * 4;
    float x1 = __ldg(bx + 0), y1 = __ldg(bx + 1);
    float x2 = __ldg(bx + 2), y2 = __ldg(bx + 3);
    Tgt o;
    o.cx = (x1 + x2) * 0.5f;
    o.cy = (y1 + y2) * 0.5f;
    o.bw = x2 - x1;
    o.bh = y2 - y1;
    o.ar = (o.bw - o.cx) * (o.bh - o.cy);    // area_t in reference

    float ar = __ldg(areas + b * T_ + t);
    float d0 = fabsf(10440.0f  - ar);        // 116*90
    float d1 = fabsf(30888.0f  - ar);        // 156*198
    float d2 = fabsf(121598.0f - ar);        // 373*326
    int   an = 0; float m = d0;
    if (d1 < m) { m = d1; an = 1; }
    if (d2 < m) { an = 2; }

    int cX = (int)((o.bw - o.cx) * 0.125f);  // /8 exact
    int cY = (int)((o.bh - o.cy) * 0.125f);
    o.key = (an << 16) | (cX << 8) | cY;

    int lab = __ldg(labels + b * T_ + t);
    o.cl = (t == 0) ? ((lab == 1) ? 1.0f : 0.0f)
                    : ((lab == 2) ? 1.0f : 0.0f);
    return o;
}

// ============================================================
// Warp-autonomous double-buffered pipeline over 128-cell rows.
// Fast path = guard + (1-conf) product; rare cells inline cold block.
// cp.async carries an L2::256B prefetch hint (sequential stream).
// ============================================================
__global__ __launch_bounds__(THREADS, 7)
void yolo_fused(const float4* __restrict__ q,
                const float*  __restrict__ boxes,
                const int*    __restrict__ labels,
                const float*  __restrict__ areas,
                float* __restrict__ out) {
    __shared__ float4 s[NWARPS][2][F4PR];      // 4 warps x 2 x 3.5 KB = 28 KB
    __shared__ int    skey[B_ * T_];
    __shared__ float  shalf[B_];               // 0.5*min(area_t0, area_t1)
    __shared__ float  red[6][NWARPS];

    const int tid  = threadIdx.x;
    const int wid  = tid >> 5;
    const int lane = tid & 31;
    const int gw   = blockIdx.x * NWARPS + wid;   // global warp id

    // per-block precompute: all 128 (b,t) keys + halved min target area
    {
        Tgt t = make_tgt(boxes, labels, areas, tid >> 1, tid & 1);
        skey[tid] = t.key;
        if ((tid & 1) == 0) {
            Tgt t1 = make_tgt(boxes, labels, areas, tid >> 1, 1);
            shalf[tid >> 1] = 0.5f * fminf(t.ar, t1.ar);
        }
    }
    __syncthreads();   // skey/shalf visible before any warp uses them

    float sx = 0.f, sy = 0.f, sw = 0.f, sh = 0.f, sc = 0.f, sl = 0.f;

    // prologue: async-load first row into this warp's buffer 0
    {
        unsigned dst = (unsigned)__cvta_generic_to_shared(&s[wid][0][lane]);
        const float4* src = q + (size_t)gw * F4PR + lane;
        #pragma unroll
        for (int m = 0; m < 7; m++)
            asm volatile("cp.async.cg.shared.global.L2::256B [%0], [%1], 16;"
                         :: "r"(dst + m * 32 * 16), "l"(src + m * 32));
        asm volatile("cp.async.commit_group;");
    }

    int buf = 0;
    for (int r = gw; r < NROWS; r += TOTWARPS) {
        // prefetch next row into the other buffer
        int nr = r + TOTWARPS;
        if (nr < NROWS) {
            unsigned dst = (unsigned)__cvta_generic_to_shared(&s[wid][buf ^ 1][lane]);
            const float4* src = q + (size_t)nr * F4PR + lane;
            #pragma unroll
            for (int m = 0; m < 7; m++)
                asm volatile("cp.async.cg.shared.global.L2::256B [%0], [%1], 16;"
                             :: "r"(dst + m * 32 * 16), "l"(src + m * 32));
        }
        asm volatile("cp.async.commit_group;");
        asm volatile("cp.async.wait_group 1;" ::: "memory");  // this row done
        __syncwarp();   // lanes see each other's cp.async data

        // row-uniform indices: r = b*384 + a*128 + i
        int b  = r / ROWS_PER_BATCH;
        int rr = r - b * ROWS_PER_BATCH;
        int a  = rr >> 7;
        int i  = rr & (H_ - 1);
        int j0 = lane * 4;

        int   k0   = skey[2 * b], k1 = skey[2 * b + 1];
        float hmin = shalf[b];

        // my 4 cells: 28 floats via 7 conflict-free LDS.128
        float f[28];
        float4* fp = reinterpret_cast<float4*>(f);
        #pragma unroll
        for (int m = 0; m < 7; m++)
            fp[m] = s[wid][buf][lane * 7 + m];

        int gkey = (a << 16) | (i << 8) | j0;
        bool gex = (gkey == (k0 & ~3)) || (gkey == (k1 & ~3));

        // ---- fast path: guard + product of (1-conf) ----
        float prod = 1.0f;
        unsigned rare = gex ? 0xFu : 0u;
        #pragma unroll
        for (int k = 0; k < 4; k++) {
            float w    = f[7 * k + 2];
            float h    = f[7 * k + 3];
            float conf = f[7 * k + 4];
            // suppress requires inter > area_t/2 and inter <= w*h:
            // w*h < 0.5*min(area_t) guarantees no suppress (exact scaling).
            bool  rb = (w * h >= hmin);
            rare |= (unsigned)rb << k;
            prod *= (rb | gex) ? 1.0f : (1.0f - conf);  // (1-conf) >= 2^-24
        }

        // ---- cold path: exact cells / possible suppress (inline) ----
        if (__builtin_expect(rare != 0u, 0)) {
            Tgt t0 = make_tgt(boxes, labels, areas, b, 0);
            Tgt t1 = make_tgt(boxes, labels, areas, b, 1);
            float fi = (float)i;
            #pragma unroll
            for (int k = 0; k < 4; k++) {
                if (!((rare >> k) & 1u)) continue;
                float xr   = f[7 * k + 0];
                float yr   = f[7 * k + 1];
                float w    = f[7 * k + 2];
                float h    = f[7 * k + 3];
                float conf = f[7 * k + 4];
                float fj   = (float)(j0 + k);
                float xp = xr - fi, yp = yr - fj;
                int key  = gkey + k;

                if (key == t1.key || key == t0.key) {
                    bool  is1 = (key == t1.key);   // target 1 wins overwrite
                    float cx = is1 ? t1.cx : t0.cx;
                    float cy = is1 ? t1.cy : t0.cy;
                    float bw = is1 ? t1.bw : t0.bw;
                    float bh = is1 ? t1.bh : t0.bh;
                    float tc = is1 ? t1.cl : t0.cl;

                    float dX = xp - (cx - fi);
                    float dY = yp - (cy - fj);
                    float dW = w - bw;
                    float dH = h - bh;
                    sx += dX * dX;  sy += dY * dY;
                    sw += dW * dW;  sh += dH * dH;

                    sc += -fmaxf(__logf(conf), -100.0f);
                    float p0 = f[7 * k + 5];
                    float p1 = f[7 * k + 6];
                    if (tc != 0.0f) {
                        sl += -fmaxf(__logf(p0), -100.0f)
                            -  fmaxf(__logf(p1), -100.0f);
                    } else {
                        sl += -fmaxf(__logf(1.0f - p0), -100.0f)
                            -  fmaxf(__logf(1.0f - p1), -100.0f);
                    }
                } else {
                    // full suppress test (division-free)
                    float hw = 0.5f * w, hh = 0.5f * h;
                    float px1 = xp - hw, px2 = xp + hw;
                    float py1 = yp - hh, py2 = yp + hh;
                    float area_p = (px2 - px1) * (py2 - py1);

                    float ix0 = fmaxf(fminf(px2, t0.bw) - fmaxf(px1, t0.cx), 0.0f);
                    float iy0 = fmaxf(fminf(py2, t0.bh) - fmaxf(py1, t0.cy), 0.0f);
                    float in0 = ix0 * iy0;
                    bool sup  = in0 > 0.5f * (area_p + t0.ar - in0 + 1e-16f);

                    float ix1 = fmaxf(fminf(px2, t1.bw) - fmaxf(px1, t1.cx), 0.0f);
                    float iy1 = fmaxf(fminf(py2, t1.bh) - fmaxf(py1, t1.cy), 0.0f);
                    float in1 = ix1 * iy1;
                    sup = sup || (in1 > 0.5f * (area_p + t1.ar - in1 + 1e-16f));

                    if (!sup)
                        sc += -fmaxf(__logf(1.0f - conf), -100.0f);
                }
            }
        }
        sc -= __logf(prod);                    // one MUFU per 4 cells

        __syncwarp();                          // all lanes done reading s[wid][buf]
        buf ^= 1;
    }

    // -- reduction: warp shuffle -> block smem -> 6 double atomics --
    #pragma unroll
    for (int o = 16; o > 0; o >>= 1) {
        sx += __shfl_down_sync(0xffffffffu, sx, o);
        sy += __shfl_down_sync(0xffffffffu, sy, o);
        sw += __shfl_down_sync(0xffffffffu, sw, o);
        sh += __shfl_down_sync(0xffffffffu, sh, o);
        sc += __shfl_down_sync(0xffffffffu, sc, o);
        sl += __shfl_down_sync(0xffffffffu, sl, o);
    }
    if (lane == 0) {
        red[0][wid] = sx; red[1][wid] = sy; red[2][wid] = sw;
        red[3][wid] = sh; red[4][wid] = sc; red[5][wid] = sl;
    }
    __syncthreads();
    if (tid < 6) {
        float acc = 0.f;
        #pragma unroll
        for (int wv = 0; wv < NWARPS; wv++) acc += red[tid][wv];
        atomicAdd(&g_acc[tid], (double)acc);
    }
    __syncthreads();

    // -- last-block-done finalization --
    if (tid == 0) {
        __threadfence();
        unsigned int old = atomicAdd(&g_done, 1u);
        if (old == gridDim.x - 1) {
            __threadfence();
            double N = (double)NCELLS;
            double xL = g_acc[0] / N;
            double yL = g_acc[1] / N;
            double wL = g_acc[2] / N;
            double hL = g_acc[3] / N;
            double confL = g_acc[4] / N;
            double clsL  = g_acc[5] / (2.0 * N);
            double loss = 2.5 * (xL + yL) + 2.5 * (wL + hL) + confL + clsL;
            out[0] = (float)loss;
            out[1] = (float)xL;
            out[2] = (float)yL;
            out[3] = (float)wL;
            out[4] = (float)hL;
            out[5] = (float)confL;
            out[6] = (float)clsL;
            #pragma unroll
            for (int i2 = 0; i2 < 6; i2++) g_acc[i2] = 0.0;
            g_done = 0;
        }
    }
}

extern "C" void kernel_launch(void* const* d_in, const int* in_sizes, int n_in,
                              void* d_out, int out_size) {
    const float* output = (const float*)d_in[0];
    const float* boxes  = (const float*)d_in[1];
    const int*   labels = (const int*)  d_in[2];
    const float* areas  = (const float*)d_in[3];

    yolo_fused<<<GRID, THREADS>>>((const float4*)output,
                                  boxes, labels, areas, (float*)d_out);
}

// round 14
// speedup vs baseline: 1.1379x; 1.0172x over previous
#include <cuda_runtime.h>

// ---- problem constants ----
#define A_   3
#define H_   128
#define W_   128
#define ATTRS 7
#define B_   64
#define T_   2
#define NCELLS (B_*A_*H_*W_)                   // 3,145,728
#define NROWS (NCELLS/W_)                      // 24576 rows of 128 cells
#define ROWS_PER_BATCH (A_*H_)                 // 384
#define THREADS 128
#define NWARPS  (THREADS/32)                   // 4
#define GRID    1036                           // 148 SMs x 7 blocks exactly
#define TOTWARPS (GRID*NWARPS)                 // 4144 warps, 5-6 rows each
#define F4PR (W_*ATTRS/4)                      // 224 float4 per row = 3584 B

// ---- persistent device state (zero-init at load; self-resetting) ----
__device__ double       g_acc[6] = {0, 0, 0, 0, 0, 0};
__device__ unsigned int g_done   = 0;

struct Tgt { float cx, cy, bw, bh, ar, cl; int key; };

__device__ __forceinline__ Tgt make_tgt(const float* __restrict__ boxes,
                                        const int*   __restrict__ labels,
                                        const float* __restrict__ areas,
                                        int b, int t) {
    const float* bx = boxes + (size_t)(b * T_ + t) * 4;
    float x1 = __ldg(bx + 0), y1 = __ldg(bx + 1);
    float x2 = __ldg(bx + 2), y2 = __ldg(bx + 3);
    Tgt o;
    o.cx = (x1 + x2) * 0.5f;
    o.cy = (y1 + y2) * 0.5f;
    o.bw = x2 - x1;
    o.bh = y2 - y1;
    o.ar = (o.bw - o.cx) * (o.bh - o.cy);    // area_t in reference

    float ar = __ldg(areas + b * T_ + t);
    float d0 = fabsf(10440.0f  - ar);        // 116*90
    float d1 = fabsf(30888.0f  - ar);        // 156*198
    float d2 = fabsf(121598.0f - ar);        // 373*326
    int   an = 0; float m = d0;
    if (d1 < m) { m = d1; an = 1; }
    if (d2 < m) { an = 2; }

    int cX = (int)((o.bw - o.cx) * 0.125f);  // /8 exact
    int cY = (int)((o.bh - o.cy) * 0.125f);
    o.key = (an << 16) | (cX << 8) | cY;

    int lab = __ldg(labels + b * T_ + t);
    o.cl = (t == 0) ? ((lab == 1) ? 1.0f : 0.0f)
                    : ((lab == 2) ? 1.0f : 0.0f);
    return o;
}

// ============================================================
// Warp-autonomous double-buffered pipeline over 128-cell rows.
// Fast path = guard + (1-conf) product; rare cells inline cold block.
// cp.async carries an L2::256B prefetch hint (sequential stream).
// ============================================================
__global__ __launch_bounds__(THREADS, 7)
void yolo_fused(const float4* __restrict__ q,
                const float*  __restrict__ boxes,
                const int*    __restrict__ labels,
                const float*  __restrict__ areas,
                float* __restrict__ out) {
    __shared__ float4 s[NWARPS][2][F4PR];      // 4 warps x 2 x 3.5 KB = 28 KB
    __shared__ int    skey[B_ * T_];
    __shared__ float  shalf[B_];               // 0.5*min(area_t0, area_t1)
    __shared__ float  red[6][NWARPS];

    const int tid  = threadIdx.x;
    const int wid  = tid >> 5;
    const int lane = tid & 31;
    const int gw   = blockIdx.x * NWARPS + wid;   // global warp id

    // per-block precompute: all 128 (b,t) keys + halved min target area
    {
        Tgt t = make_tgt(boxes, labels, areas, tid >> 1, tid & 1);
        skey[tid] = t.key;
        if ((tid & 1) == 0) {
            Tgt t1 = make_tgt(boxes, labels, areas, tid >> 1, 1);
            shalf[tid >> 1] = 0.5f * fminf(t.ar, t1.ar);
        }
    }
    __syncthreads();   // skey/shalf visible before any warp uses them

    float sx = 0.f, sy = 0.f, sw = 0.f, sh = 0.f, sc = 0.f, sl = 0.f;

    // prologue: async-load first row into this warp's buffer 0
    if (gw < NROWS) {
        unsigned dst = (unsigned)__cvta_generic_to_shared(&s[wid][0][lane]);
        const float4* src = q + (size_t)gw * F4PR + lane;
        #pragma unroll
        for (int m = 0; m < 7; m++)
            asm volatile("cp.async.cg.shared.global.L2::256B [%0], [%1], 16;"
                         :: "r"(dst + m * 32 * 16), "l"(src + m * 32));
    }
    asm volatile("cp.async.commit_group;");

    int buf = 0;
    for (int r = gw; r < NROWS; r += TOTWARPS) {
        // prefetch next row into the other buffer
        int nr = r + TOTWARPS;
        if (nr < NROWS) {
            unsigned dst = (unsigned)__cvta_generic_to_shared(&s[wid][buf ^ 1][lane]);
            const float4* src = q + (size_t)nr * F4PR + lane;
            #pragma unroll
            for (int m = 0; m < 7; m++)
                asm volatile("cp.async.cg.shared.global.L2::256B [%0], [%1], 16;"
                             :: "r"(dst + m * 32 * 16), "l"(src + m * 32));
        }
        asm volatile("cp.async.commit_group;");
        asm volatile("cp.async.wait_group 1;" ::: "memory");  // this row done
        __syncwarp();   // lanes see each other's cp.async data

        // row-uniform indices: r = b*384 + a*128 + i
        int b  = r / ROWS_PER_BATCH;
        int rr = r - b * ROWS_PER_BATCH;
        int a  = rr >> 7;
        int i  = rr & (H_ - 1);
        int j0 = lane * 4;

        int   k0   = skey[2 * b], k1 = skey[2 * b + 1];
        float hmin = shalf[b];

        // my 4 cells: 28 floats via 7 conflict-free LDS.128
        float f[28];
        float4* fp = reinterpret_cast<float4*>(f);
        #pragma unroll
        for (int m = 0; m < 7; m++)
            fp[m] = s[wid][buf][lane * 7 + m];

        int gkey = (a << 16) | (i << 8) | j0;
        bool gex = (gkey == (k0 & ~3)) || (gkey == (k1 & ~3));

        // ---- fast path: guard + product of (1-conf) ----
        float prod = 1.0f;
        unsigned rare = gex ? 0xFu : 0u;
        #pragma unroll
        for (int k = 0; k < 4; k++) {
            float w    = f[7 * k + 2];
            float h    = f[7 * k + 3];
            float conf = f[7 * k + 4];
            // suppress requires inter > area_t/2 and inter <= w*h:
            // w*h < 0.5*min(area_t) guarantees no suppress (exact scaling).
            bool  rb = (w * h >= hmin);
            rare |= (unsigned)rb << k;
            prod *= (rb | gex) ? 1.0f : (1.0f - conf);  // (1-conf) >= 2^-24
        }

        // ---- cold path: exact cells / possible suppress (inline) ----
        if (__builtin_expect(rare != 0u, 0)) {
            Tgt t0 = make_tgt(boxes, labels, areas, b, 0);
            Tgt t1 = make_tgt(boxes, labels, areas, b, 1);
            float fi = (float)i;
            #pragma unroll
            for (int k = 0; k < 4; k++) {
                if (!((rare >> k) & 1u)) continue;
                float xr   = f[7 * k + 0];
                float yr   = f[7 * k + 1];
                float w    = f[7 * k + 2];
                float h    = f[7 * k + 3];
                float conf = f[7 * k + 4];
                float fj   = (float)(j0 + k);
                float xp = xr - fi, yp = yr - fj;
                int key  = gkey + k;

                if (key == t1.key || key == t0.key) {
                    bool  is1 = (key == t1.key);   // target 1 wins overwrite
                    float cx = is1 ? t1.cx : t0.cx;
                    float cy = is1 ? t1.cy : t0.cy;
                    float bw = is1 ? t1.bw : t0.bw;
                    float bh = is1 ? t1.bh : t0.bh;
                    float tc = is1 ? t1.cl : t0.cl;

                    float dX = xp - (cx - fi);
                    float dY = yp - (cy - fj);
                    float dW = w - bw;
                    float dH = h - bh;
                    sx += dX * dX;  sy += dY * dY;
                    sw += dW * dW;  sh += dH * dH;

                    sc += -fmaxf(__logf(conf), -100.0f);
                    float p0 = f[7 * k + 5];
                    float p1 = f[7 * k + 6];
                    if (tc != 0.0f) {
                        sl += -fmaxf(__logf(p0), -100.0f)
                            -  fmaxf(__logf(p1), -100.0f);
                    } else {
                        sl += -fmaxf(__logf(1.0f - p0), -100.0f)
                            -  fmaxf(__logf(1.0f - p1), -100.0f);
                    }
                } else {
                    // full suppress test (division-free)
                    float hw = 0.5f * w, hh = 0.5f * h;
                    float px1 = xp - hw, px2 = xp + hw;
                    float py1 = yp - hh, py2 = yp + hh;
                    float area_p = (px2 - px1) * (py2 - py1);

                    float ix0 = fmaxf(fminf(px2, t0.bw) - fmaxf(px1, t0.cx), 0.0f);
                    float iy0 = fmaxf(fminf(py2, t0.bh) - fmaxf(py1, t0.cy), 0.0f);
                    float in0 = ix0 * iy0;
                    bool sup  = in0 > 0.5f * (area_p + t0.ar - in0 + 1e-16f);

                    float ix1 = fmaxf(fminf(px2, t1.bw) - fmaxf(px1, t1.cx), 0.0f);
                    float iy1 = fmaxf(fminf(py2, t1.bh) - fmaxf(py1, t1.cy), 0.0f);
                    float in1 = ix1 * iy1;
                    sup = sup || (in1 > 0.5f * (area_p + t1.ar - in1 + 1e-16f));

                    if (!sup)
                        sc += -fmaxf(__logf(1.0f - conf), -100.0f);
                }
            }
        }
        sc -= __logf(prod);                    // one MUFU per 4 cells

        __syncwarp();                          // all lanes done reading s[wid][buf]
        buf ^= 1;
    }

    // -- reduction: warp shuffle -> block smem -> 6 double atomics --
    #pragma unroll
    for (int o = 16; o > 0; o >>= 1) {
        sx += __shfl_down_sync(0xffffffffu, sx, o);
        sy += __shfl_down_sync(0xffffffffu, sy, o);
        sw += __shfl_down_sync(0xffffffffu, sw, o);
        sh += __shfl_down_sync(0xffffffffu, sh, o);
        sc += __shfl_down_sync(0xffffffffu, sc, o);
        sl += __shfl_down_sync(0xffffffffu, sl, o);
    }
    if (lane == 0) {
        red[0][wid] = sx; red[1][wid] = sy; red[2][wid] = sw;
        red[3][wid] = sh; red[4][wid] = sc; red[5][wid] = sl;
    }
    __syncthreads();
    if (tid < 6) {
        float acc = 0.f;
        #pragma unroll
        for (int wv = 0; wv < NWARPS; wv++) acc += red[tid][wv];
        atomicAdd(&g_acc[tid], (double)acc);
    }
    __syncthreads();

    // -- last-block-done finalization --
    if (tid == 0) {
        __threadfence();
        unsigned int old = atomicAdd(&g_done, 1u);
        if (old == gridDim.x - 1) {
            __threadfence();
            double N = (double)NCELLS;
            double xL = g_acc[0] / N;
            double yL = g_acc[1] / N;
            double wL = g_acc[2] / N;
            double hL = g_acc[3] / N;
            double confL = g_acc[4] / N;
            double clsL  = g_acc[5] / (2.0 * N);
            double loss = 2.5 * (xL + yL) + 2.5 * (wL + hL) + confL + clsL;
            out[0] = (float)loss;
            out[1] = (float)xL;
            out[2] = (float)yL;
            out[3] = (float)wL;
            out[4] = (float)hL;
            out[5] = (float)confL;
            out[6] = (float)clsL;
            #pragma unroll
            for (int i2 = 0; i2 < 6; i2++) g_acc[i2] = 0.0;
            g_done = 0;
        }
    }
}

extern "C" void kernel_launch(void* const* d_in, const int* in_sizes, int n_in,
                              void* d_out, int out_size) {
    const float* output = (const float*)d_in[0];
    const float* boxes  = (const float*)d_in[1];
    const int*   labels = (const int*)  d_in[2];
    const float* areas  = (const float*)d_in[3];

    yolo_fused<<<GRID, THREADS>>>((const float4*)output,
                                  boxes, labels, areas, (float*)d_out);
}

// round 15
// speedup vs baseline: 1.1404x; 1.0022x over previous
#include <cuda_runtime.h>

// ---- problem constants ----
#define A_   3
#define H_   128
#define W_   128
#define ATTRS 7
#define B_   64
#define T_   2
#define NCELLS (B_*A_*H_*W_)                   // 3,145,728
#define NROWS (NCELLS/W_)                      // 24576 rows of 128 cells
#define ROWS_PER_BATCH (A_*H_)                 // 384
#define THREADS 128
#define NWARPS  (THREADS/32)                   // 4
#define GRID    1036                           // 148 SMs x 7 blocks exactly
#define TOTWARPS (GRID*NWARPS)                 // 4144 warps, 5-6 rows each
#define F4PR (W_*ATTRS/4)                      // 224 float4 per row = 3584 B

// ---- persistent device state (zero-init at load; self-resetting) ----
__device__ double       g_acc[6] = {0, 0, 0, 0, 0, 0};
__device__ unsigned int g_done   = 0;

struct Tgt { float cx, cy, bw, bh, ar, cl; int key; };

__device__ __forceinline__ Tgt make_tgt(const float* __restrict__ boxes,
                                        const int*   __restrict__ labels,
                                        const float* __restrict__ areas,
                                        int b, int t) {
    const float* bx = boxes + (size_t)(b * T_ + t) * 4;
    float x1 = __ldg(bx + 0), y1 = __ldg(bx + 1);
    float x2 = __ldg(bx + 2), y2 = __ldg(bx + 3);
    Tgt o;
    o.cx = (x1 + x2) * 0.5f;
    o.cy = (y1 + y2) * 0.5f;
    o.bw = x2 - x1;
    o.bh = y2 - y1;
    o.ar = (o.bw - o.cx) * (o.bh - o.cy);    // area_t in reference

    float ar = __ldg(areas + b * T_ + t);
    float d0 = fabsf(10440.0f  - ar);        // 116*90
    float d1 = fabsf(30888.0f  - ar);        // 156*198
    float d2 = fabsf(121598.0f - ar);        // 373*326
    int   an = 0; float m = d0;
    if (d1 < m) { m = d1; an = 1; }
    if (d2 < m) { an = 2; }

    int cX = (int)((o.bw - o.cx) * 0.125f);  // /8 exact
    int cY = (int)((o.bh - o.cy) * 0.125f);
    o.key = (an << 16) | (cX << 8) | cY;

    int lab = __ldg(labels + b * T_ + t);
    o.cl = (t == 0) ? ((lab == 1) ? 1.0f : 0.0f)
                    : ((lab == 2) ? 1.0f : 0.0f);
    return o;
}

// ============================================================
// Warp-autonomous double-buffered pipeline over 128-cell rows.
// Fast path = guard + (1-conf) product; rare cells inline cold block.
// cp.async carries an L2::256B prefetch hint (sequential stream).
// Final atomics skipped when the partial sum is exactly zero.
// ============================================================
__global__ __launch_bounds__(THREADS, 7)
void yolo_fused(const float4* __restrict__ q,
                const float*  __restrict__ boxes,
                const int*    __restrict__ labels,
                const float*  __restrict__ areas,
                float* __restrict__ out) {
    __shared__ float4 s[NWARPS][2][F4PR];      // 4 warps x 2 x 3.5 KB = 28 KB
    __shared__ int    skey[B_ * T_];
    __shared__ float  shalf[B_];               // 0.5*min(area_t0, area_t1)
    __shared__ float  red[6][NWARPS];

    const int tid  = threadIdx.x;
    const int wid  = tid >> 5;
    const int lane = tid & 31;
    const int gw   = blockIdx.x * NWARPS + wid;   // global warp id

    // per-block precompute: all 128 (b,t) keys + halved min target area
    {
        Tgt t = make_tgt(boxes, labels, areas, tid >> 1, tid & 1);
        skey[tid] = t.key;
        if ((tid & 1) == 0) {
            Tgt t1 = make_tgt(boxes, labels, areas, tid >> 1, 1);
            shalf[tid >> 1] = 0.5f * fminf(t.ar, t1.ar);
        }
    }
    __syncthreads();   // skey/shalf visible before any warp uses them

    float sx = 0.f, sy = 0.f, sw = 0.f, sh = 0.f, sc = 0.f, sl = 0.f;

    // prologue: async-load first row into this warp's buffer 0
    if (gw < NROWS) {
        unsigned dst = (unsigned)__cvta_generic_to_shared(&s[wid][0][lane]);
        const float4* src = q + (size_t)gw * F4PR + lane;
        #pragma unroll
        for (int m = 0; m < 7; m++)
            asm volatile("cp.async.cg.shared.global.L2::256B [%0], [%1], 16;"
                         :: "r"(dst + m * 32 * 16), "l"(src + m * 32));
    }
    asm volatile("cp.async.commit_group;");

    int buf = 0;
    for (int r = gw; r < NROWS; r += TOTWARPS) {
        // prefetch next row into the other buffer
        int nr = r + TOTWARPS;
        if (nr < NROWS) {
            unsigned dst = (unsigned)__cvta_generic_to_shared(&s[wid][buf ^ 1][lane]);
            const float4* src = q + (size_t)nr * F4PR + lane;
            #pragma unroll
            for (int m = 0; m < 7; m++)
                asm volatile("cp.async.cg.shared.global.L2::256B [%0], [%1], 16;"
                             :: "r"(dst + m * 32 * 16), "l"(src + m * 32));
        }
        asm volatile("cp.async.commit_group;");
        asm volatile("cp.async.wait_group 1;" ::: "memory");  // this row done
        __syncwarp();   // lanes see each other's cp.async data

        // row-uniform indices: r = b*384 + a*128 + i
        int b  = r / ROWS_PER_BATCH;
        int rr = r - b * ROWS_PER_BATCH;
        int a  = rr >> 7;
        int i  = rr & (H_ - 1);
        int j0 = lane * 4;

        int   k0   = skey[2 * b], k1 = skey[2 * b + 1];
        float hmin = shalf[b];

        // my 4 cells: 28 floats via 7 conflict-free LDS.128
        float f[28];
        float4* fp = reinterpret_cast<float4*>(f);
        #pragma unroll
        for (int m = 0; m < 7; m++)
            fp[m] = s[wid][buf][lane * 7 + m];

        int gkey = (a << 16) | (i << 8) | j0;
        bool gex = (gkey == (k0 & ~3)) || (gkey == (k1 & ~3));

        // ---- fast path: guard + product of (1-conf) ----
        float prod = 1.0f;
        unsigned rare = gex ? 0xFu : 0u;
        #pragma unroll
        for (int k = 0; k < 4; k++) {
            float w    = f[7 * k + 2];
            float h    = f[7 * k + 3];
            float conf = f[7 * k + 4];
            // suppress requires inter > area_t/2 and inter <= w*h:
            // w*h < 0.5*min(area_t) guarantees no suppress (exact scaling).
            bool  rb = (w * h >= hmin);
            rare |= (unsigned)rb << k;
            prod *= (rb | gex) ? 1.0f : (1.0f - conf);  // (1-conf) >= 2^-24
        }

        // ---- cold path: exact cells / possible suppress (inline) ----
        if (__builtin_expect(rare != 0u, 0)) {
            Tgt t0 = make_tgt(boxes, labels, areas, b, 0);
            Tgt t1 = make_tgt(boxes, labels, areas, b, 1);
            float fi = (float)i;
            #pragma unroll
            for (int k = 0; k < 4; k++) {
                if (!((rare >> k) & 1u)) continue;
                float xr   = f[7 * k + 0];
                float yr   = f[7 * k + 1];
                float w    = f[7 * k + 2];
                float h    = f[7 * k + 3];
                float conf = f[7 * k + 4];
                float fj   = (float)(j0 + k);
                float xp = xr - fi, yp = yr - fj;
                int key  = gkey + k;

                if (key == t1.key || key == t0.key) {
                    bool  is1 = (key == t1.key);   // target 1 wins overwrite
                    float cx = is1 ? t1.cx : t0.cx;
                    float cy = is1 ? t1.cy : t0.cy;
                    float bw = is1 ? t1.bw : t0.bw;
                    float bh = is1 ? t1.bh : t0.bh;
                    float tc = is1 ? t1.cl : t0.cl;

                    float dX = xp - (cx - fi);
                    float dY = yp - (cy - fj);
                    float dW = w - bw;
                    float dH = h - bh;
                    sx += dX * dX;  sy += dY * dY;
                    sw += dW * dW;  sh += dH * dH;

                    sc += -fmaxf(__logf(conf), -100.0f);
                    float p0 = f[7 * k + 5];
                    float p1 = f[7 * k + 6];
                    if (tc != 0.0f) {
                        sl += -fmaxf(__logf(p0), -100.0f)
                            -  fmaxf(__logf(p1), -100.0f);
                    } else {
                        sl += -fmaxf(__logf(1.0f - p0), -100.0f)
                            -  fmaxf(__logf(1.0f - p1), -100.0f);
                    }
                } else {
                    // full suppress test (division-free)
                    float hw = 0.5f * w, hh = 0.5f * h;
                    float px1 = xp - hw, px2 = xp + hw;
                    float py1 = yp - hh, py2 = yp + hh;
                    float area_p = (px2 - px1) * (py2 - py1);

                    float ix0 = fmaxf(fminf(px2, t0.bw) - fmaxf(px1, t0.cx), 0.0f);
                    float iy0 = fmaxf(fminf(py2, t0.bh) - fmaxf(py1, t0.cy), 0.0f);
                    float in0 = ix0 * iy0;
                    bool sup  = in0 > 0.5f * (area_p + t0.ar - in0 + 1e-16f);

                    float ix1 = fmaxf(fminf(px2, t1.bw) - fmaxf(px1, t1.cx), 0.0f);
                    float iy1 = fmaxf(fminf(py2, t1.bh) - fmaxf(py1, t1.cy), 0.0f);
                    float in1 = ix1 * iy1;
                    sup = sup || (in1 > 0.5f * (area_p + t1.ar - in1 + 1e-16f));

                    if (!sup)
                        sc += -fmaxf(__logf(1.0f - conf), -100.0f);
                }
            }
        }
        sc -= __logf(prod);                    // one MUFU per 4 cells

        __syncwarp();                          // all lanes done reading s[wid][buf]
        buf ^= 1;
    }

    // -- reduction: warp shuffle -> block smem -> sparse double atomics --
    #pragma unroll
    for (int o = 16; o > 0; o >>= 1) {
        sx += __shfl_down_sync(0xffffffffu, sx, o);
        sy += __shfl_down_sync(0xffffffffu, sy, o);
        sw += __shfl_down_sync(0xffffffffu, sw, o);
        sh += __shfl_down_sync(0xffffffffu, sh, o);
        sc += __shfl_down_sync(0xffffffffu, sc, o);
        sl += __shfl_down_sync(0xffffffffu, sl, o);
    }
    if (lane == 0) {
        red[0][wid] = sx; red[1][wid] = sy; red[2][wid] = sw;
        red[3][wid] = sh; red[4][wid] = sc; red[5][wid] = sl;
    }
    __syncthreads();
    if (tid < 6) {
        float acc = 0.f;
        #pragma unroll
        for (int wv = 0; wv < NWARPS; wv++) acc += red[tid][wv];
        // sx/sy/sw/sh/sl are exactly 0 in all blocks without an exact cell
        // (<=~120 of 1036 blocks have one) — skip the no-op atomics.
        if (acc != 0.0f)
            atomicAdd(&g_acc[tid], (double)acc);
    }
    __syncthreads();

    // -- last-block-done finalization --
    if (tid == 0) {
        __threadfence();
        unsigned int old = atomicAdd(&g_done, 1u);
        if (old == gridDim.x - 1) {
            __threadfence();
            double N = (double)NCELLS;
            double xL = g_acc[0] / N;
            double yL = g_acc[1] / N;
            double wL = g_acc[2] / N;
            double hL = g_acc[3] / N;
            double confL = g_acc[4] / N;
            double clsL  = g_acc[5] / (2.0 * N);
            double loss = 2.5 * (xL + yL) + 2.5 * (wL + hL) + confL + clsL;
            out[0] = (float)loss;
            out[1] = (float)xL;
            out[2] = (float)yL;
            out[3] = (float)wL;
            out[4] = (float)hL;
            out[5] = (float)confL;
            out[6] = (float)clsL;
            #pragma unroll
            for (int i2 = 0; i2 < 6; i2++) g_acc[i2] = 0.0;
            g_done = 0;
        }
    }
}

extern "C" void kernel_launch(void* const* d_in, const int* in_sizes, int n_in,
                              void* d_out, int out_size) {
    const float* output = (const float*)d_in[0];
    const float* boxes  = (const float*)d_in[1];
    const int*   labels = (const int*)  d_in[2];
    const float* areas  = (const float*)d_in[3];

    yolo_fused<<<GRID, THREADS>>>((const float4*)output,
                                  boxes, labels, areas, (float*)d_out);
}